// round 10
// baseline (speedup 1.0000x reference)
#include <cuda_runtime.h>
#include <cuda_bf16.h>
#include <cstdint>

#define NPTS 12288
#define DIM 16
#define NT 96                         // number of 128-point tiles
#define NPAIRS (NT * (NT + 1) / 2)    // 4656 triangle tiles
#define TPB 256
#define SOP_BLK 256
#define SOP_BLOCKS (NPTS / SOP_BLK)   // 48

// ---- scratch (__device__ globals; no allocation allowed) ------------------
// g_part[s][p] = (se, sw) contribution to point p from tile s's 128 partners.
// Each (s,p) written by exactly ONE block: row-path if tile(p) <= s,
// col-path if s < tile(p). Deterministic, no atomics.
__device__ float2 g_part[NT][NPTS];         // 9.4 MB
__device__ float g_Mpart[SOP_BLOCKS][256];  // per-block SOP partials
__device__ unsigned int g_cnt = 0;          // last-block counter (self-resetting)

__device__ __forceinline__ float ex2_approx(float x) {
    float r; asm("ex2.approx.ftz.f32 %0, %1;" : "=f"(r) : "f"(x)); return r;
}
__device__ __forceinline__ uint32_t bf2_u32(__nv_bfloat162 v) {
    return *reinterpret_cast<uint32_t*>(&v);
}

// ---------------------------------------------------------------------------
// Kernel 1: symmetric tiled attention stats. Block = one 128x128 tile (i,j),
// i<=j. Each exp serves BOTH row q (se_q,sw_q) and col k (se_k,sw_k) stats
// -> half the exps of the dense version. Warp owns 16 keys (B frags loaded
// once); loops 8 row-groups x 2 MMAs. Col partials accumulate in registers
// across row-groups (one 24-shfl reduce per tile); row partials use a
// 2-shfl tig-reduce per row-group + smem cross-warp combine.
// t = score*log2(e) (A pre-scaled); e = 2^t; se += e; sw += e*t.
// Identity: <ctx_q,f_q> = 4*ln2 * sw_q/se_q.
// ---------------------------------------------------------------------------
__global__ void __launch_bounds__(TPB) attn_tile_kernel(const float* __restrict__ feats) {
    __shared__ uint32_t sA[128 * 12];       // queries bf16x2, scaled, stride-12 u32 (conflict-free)
    __shared__ uint32_t sB[128 * 12];       // keys bf16x2, unscaled
    __shared__ float2 rowpart[8][128];      // per-warp row partials

    // decode linear block id -> triangle tile (i, j), i <= j
    int i = 0, rem = blockIdx.x;
    while (rem >= NT - i) { rem -= NT - i; i++; }
    const int j = i + rem;
    const bool diag = (i == j);

    const int tid  = threadIdx.x;
    const int warp = tid >> 5;
    const int lane = tid & 31;
    const int g    = lane >> 2;             // 0..7
    const int tig  = lane & 3;              // 0..3

    // ---- stage both tiles, converting f32 -> bf16 on the fly ----
    {
        const float sc = 0.25f * 1.4426950408889634f;
        const float4* fa = reinterpret_cast<const float4*>(feats) + i * 128 * 4;
        const float4* fb = reinterpret_cast<const float4*>(feats) + j * 128 * 4;
        #pragma unroll
        for (int t = tid; t < 512; t += TPB) {
            int row = t >> 2, f = t & 3;
            float4 va = fa[t];
            float4 vb = fb[t];
            uint2 ua = make_uint2(bf2_u32(__floats2bfloat162_rn(va.x * sc, va.y * sc)),
                                  bf2_u32(__floats2bfloat162_rn(va.z * sc, va.w * sc)));
            uint2 ub = make_uint2(bf2_u32(__floats2bfloat162_rn(vb.x, vb.y)),
                                  bf2_u32(__floats2bfloat162_rn(vb.z, vb.w)));
            *reinterpret_cast<uint2*>(&sA[row * 12 + 2 * f]) = ua;
            *reinterpret_cast<uint2*>(&sB[row * 12 + 2 * f]) = ub;
        }
    }
    __syncthreads();

    // ---- B fragments for this warp's 16 keys (loaded once) ----
    const int wkey = warp * 16;
    const uint32_t b00 = sB[(wkey + g) * 12 + tig];
    const uint32_t b01 = sB[(wkey + g) * 12 + tig + 4];
    const uint32_t b10 = sB[(wkey + 8 + g) * 12 + tig];
    const uint32_t b11 = sB[(wkey + 8 + g) * 12 + tig + 4];

    // col accumulators: keys wkey + {2tig, 2tig+1, 8+2tig, 9+2tig}
    float ce0 = 0.f, ce1 = 0.f, ce2 = 0.f, ce3 = 0.f;
    float cw0 = 0.f, cw1 = 0.f, cw2 = 0.f, cw3 = 0.f;

    #pragma unroll
    for (int rg = 0; rg < 8; rg++) {
        const int r0 = rg * 16;
        uint32_t a0 = sA[(r0 + g) * 12 + tig];
        uint32_t a1 = sA[(r0 + 8 + g) * 12 + tig];
        uint32_t a2 = sA[(r0 + g) * 12 + tig + 4];
        uint32_t a3 = sA[(r0 + 8 + g) * 12 + tig + 4];

        float er0, er1, pr0, pr1;
        {   // MMA 1: keys wkey + 2tig, wkey + 2tig + 1
            float d0, d1, d2, d3;
            asm volatile(
                "mma.sync.aligned.m16n8k16.row.col.f32.bf16.bf16.f32 "
                "{%0,%1,%2,%3}, {%4,%5,%6,%7}, {%8,%9}, {%10,%11,%12,%13};"
                : "=f"(d0), "=f"(d1), "=f"(d2), "=f"(d3)
                : "r"(a0), "r"(a1), "r"(a2), "r"(a3), "r"(b00), "r"(b01),
                  "f"(0.0f), "f"(0.0f), "f"(0.0f), "f"(0.0f));
            float e0 = ex2_approx(d0), e1 = ex2_approx(d1);
            float e2 = ex2_approx(d2), e3 = ex2_approx(d3);
            float p0 = e0 * d0, p1 = e1 * d1, p2 = e2 * d2, p3 = e3 * d3;
            er0 = e0 + e1; pr0 = p0 + p1;     // row r0+g
            er1 = e2 + e3; pr1 = p2 + p3;     // row r0+8+g
            ce0 += e0 + e2; cw0 += p0 + p2;   // key wkey+2tig
            ce1 += e1 + e3; cw1 += p1 + p3;   // key wkey+2tig+1
        }
        {   // MMA 2: keys wkey + 8 + 2tig, wkey + 9 + 2tig
            float d0, d1, d2, d3;
            asm volatile(
                "mma.sync.aligned.m16n8k16.row.col.f32.bf16.bf16.f32 "
                "{%0,%1,%2,%3}, {%4,%5,%6,%7}, {%8,%9}, {%10,%11,%12,%13};"
                : "=f"(d0), "=f"(d1), "=f"(d2), "=f"(d3)
                : "r"(a0), "r"(a1), "r"(a2), "r"(a3), "r"(b10), "r"(b11),
                  "f"(0.0f), "f"(0.0f), "f"(0.0f), "f"(0.0f));
            float e0 = ex2_approx(d0), e1 = ex2_approx(d1);
            float e2 = ex2_approx(d2), e3 = ex2_approx(d3);
            float p0 = e0 * d0, p1 = e1 * d1, p2 = e2 * d2, p3 = e3 * d3;
            er0 += e0 + e1; pr0 += p0 + p1;
            er1 += e2 + e3; pr1 += p2 + p3;
            ce2 += e0 + e2; cw2 += p0 + p2;
            ce3 += e1 + e3; cw3 += p1 + p3;
        }

        // row reduce across the 4 tig lanes of each row-quad
        er0 += __shfl_xor_sync(0xffffffffu, er0, 1);
        er0 += __shfl_xor_sync(0xffffffffu, er0, 2);
        pr0 += __shfl_xor_sync(0xffffffffu, pr0, 1);
        pr0 += __shfl_xor_sync(0xffffffffu, pr0, 2);
        er1 += __shfl_xor_sync(0xffffffffu, er1, 1);
        er1 += __shfl_xor_sync(0xffffffffu, er1, 2);
        pr1 += __shfl_xor_sync(0xffffffffu, pr1, 1);
        pr1 += __shfl_xor_sync(0xffffffffu, pr1, 2);
        if (tig == 0) {
            rowpart[warp][r0 + g]     = make_float2(er0, pr0);
            rowpart[warp][r0 + 8 + g] = make_float2(er1, pr1);
        }
    }
    __syncthreads();

    // row stats: combine across warps -> slot j, points i*128 + row
    if (tid < 128) {
        float se = 0.f, sw = 0.f;
        #pragma unroll
        for (int w = 0; w < 8; w++) {
            float2 v = rowpart[w][tid];
            se += v.x; sw += v.y;
        }
        g_part[j][i * 128 + tid] = make_float2(se, sw);
    }

    // col stats: reduce over the 8 g-groups, write slot i, points j*128 + key.
    // Skipped on diagonal tiles (row stats already cover the full tile).
    if (!diag) {
        #pragma unroll
        for (int m = 4; m <= 16; m <<= 1) {
            ce0 += __shfl_xor_sync(0xffffffffu, ce0, m);
            cw0 += __shfl_xor_sync(0xffffffffu, cw0, m);
            ce1 += __shfl_xor_sync(0xffffffffu, ce1, m);
            cw1 += __shfl_xor_sync(0xffffffffu, cw1, m);
            ce2 += __shfl_xor_sync(0xffffffffu, ce2, m);
            cw2 += __shfl_xor_sync(0xffffffffu, cw2, m);
            ce3 += __shfl_xor_sync(0xffffffffu, ce3, m);
            cw3 += __shfl_xor_sync(0xffffffffu, cw3, m);
        }
        if (g == 0) {
            const int kb = j * 128 + wkey;
            g_part[i][kb + 2 * tig]     = make_float2(ce0, cw0);
            g_part[i][kb + 2 * tig + 1] = make_float2(ce1, cw1);
            g_part[i][kb + 8 + 2 * tig] = make_float2(ce2, cw2);
            g_part[i][kb + 9 + 2 * tig] = make_float2(ce3, cw3);
        }
    }
}

// ---------------------------------------------------------------------------
// Kernel 2: reduce the 96 partial slots; w = sigmoid(4*ln2 * sw/se);
// block-local SOP partial M_b = sum_i w_i^2 f_i f_i^T; LAST block (atomic
// counter) reduces partials, L2-normalizes, writes 256-float output.
// (topK=1 -> all points kept; /k cancels in the L2-normalize.)
// ---------------------------------------------------------------------------
__global__ void __launch_bounds__(SOP_BLK) sop_kernel(const float* __restrict__ feats,
                                                      float* __restrict__ out) {
    __shared__ float sf[SOP_BLK][DIM];
    __shared__ float sw2[SOP_BLK];
    __shared__ unsigned int isLast;

    const int tid = threadIdx.x;
    const int b   = blockIdx.x;
    const int p   = b * SOP_BLK + tid;

    float se = 0.0f, sw = 0.0f;
    #pragma unroll 8
    for (int s = 0; s < NT; s++) {
        float2 v = g_part[s][p];
        se += v.x; sw += v.y;
    }
    const float c4ln2 = 4.0f * 0.6931471805599453f;
    float cf = c4ln2 * sw / se;
    float w = 1.0f / (1.0f + __expf(-cf));
    sw2[tid] = w * w;

    const float4* fp = reinterpret_cast<const float4*>(feats) + p * 4;
    float4 f0 = fp[0], f1 = fp[1], f2 = fp[2], f3 = fp[3];
    sf[tid][0]  = f0.x; sf[tid][1]  = f0.y; sf[tid][2]  = f0.z; sf[tid][3]  = f0.w;
    sf[tid][4]  = f1.x; sf[tid][5]  = f1.y; sf[tid][6]  = f1.z; sf[tid][7]  = f1.w;
    sf[tid][8]  = f2.x; sf[tid][9]  = f2.y; sf[tid][10] = f2.z; sf[tid][11] = f2.w;
    sf[tid][12] = f3.x; sf[tid][13] = f3.y; sf[tid][14] = f3.z; sf[tid][15] = f3.w;
    __syncthreads();

    const int d = tid >> 4;
    const int e = tid & 15;
    float acc = 0.0f;
    #pragma unroll 8
    for (int i = 0; i < SOP_BLK; i++) {
        acc = fmaf(sw2[i] * sf[i][d], sf[i][e], acc);
    }
    g_Mpart[b][tid] = acc;

    // ---- last-block finalize (deterministic; counter self-resets) ----
    __threadfence();
    if (tid == 0) isLast = (atomicAdd(&g_cnt, 1u) == SOP_BLOCKS - 1) ? 1u : 0u;
    __syncthreads();
    if (isLast) {
        __threadfence();
        float v = 0.0f;
        #pragma unroll 8
        for (int bb = 0; bb < SOP_BLOCKS; bb++) v += g_Mpart[bb][tid];

        __syncthreads();          // sw2 reuse safe
        sw2[tid] = v * v;
        __syncthreads();
        #pragma unroll
        for (int o = 128; o > 0; o >>= 1) {
            if (tid < o) sw2[tid] += sw2[tid + o];
            __syncthreads();
        }
        float inv = 1.0f / sqrtf(sw2[0]);
        out[tid] = v * inv;
        if (tid == 0) g_cnt = 0;
    }
}

// ---------------------------------------------------------------------------
extern "C" void kernel_launch(void* const* d_in, const int* in_sizes, int n_in,
                              void* d_out, int out_size) {
    const float* feats = (const float*)d_in[0];
    float* out = (float*)d_out;

    attn_tile_kernel<<<NPAIRS, TPB>>>(feats);
    sop_kernel<<<SOP_BLOCKS, SOP_BLK>>>(feats, out);
}

// round 11
// speedup vs baseline: 1.0500x; 1.0500x over previous
#include <cuda_runtime.h>
#include <cuda_bf16.h>
#include <cstdint>

#define NPTS 12288
#define DIM 16
#define NT 96                         // number of 128-point tiles
#define NPAIRS (NT * (NT + 1) / 2)    // 4656 triangle tiles
#define TPB 256
#define SOP_BLK 256
#define SOP_BLOCKS (NPTS / SOP_BLK)   // 48

typedef unsigned long long u64;

// ---- scratch (__device__ globals; no allocation allowed) ------------------
// g_part[s][p] = (se, sw) contribution to point p from tile s's 128 partners.
// Each (s,p) written by exactly ONE block (row-path if tile(p) <= s, col-path
// if s < tile(p)). Deterministic, no atomics.
__device__ float2 g_part[NT][NPTS];         // 9.4 MB
__device__ float g_w2[NPTS];                // per-point w^2
__device__ float g_Mpart[SOP_BLOCKS][256];  // per-block SOP partials
__device__ unsigned int g_cnt = 0;          // last-block counter (self-resetting)

__device__ __forceinline__ float ex2_approx(float x) {
    float r; asm("ex2.approx.ftz.f32 %0, %1;" : "=f"(r) : "f"(x)); return r;
}
__device__ __forceinline__ uint32_t bf2_u32(__nv_bfloat162 v) {
    return *reinterpret_cast<uint32_t*>(&v);
}
__device__ __forceinline__ u64 pack2(float lo, float hi) {
    u64 r; asm("mov.b64 %0, {%1, %2};" : "=l"(r) : "f"(lo), "f"(hi)); return r;
}
__device__ __forceinline__ void unpack2(u64 v, float& lo, float& hi) {
    asm("mov.b64 {%0, %1}, %2;" : "=f"(lo), "=f"(hi) : "l"(v));
}
__device__ __forceinline__ u64 add2(u64 a, u64 b) {
    u64 d; asm("add.rn.f32x2 %0, %1, %2;" : "=l"(d) : "l"(a), "l"(b)); return d;
}

// ---------------------------------------------------------------------------
// Kernel 1: symmetric tiled attention stats, packed-f32x2 epilogue.
// Block = one 128x128 tile (i,j), i<=j; each exp serves BOTH its row and its
// column stats (half the exps of dense). Per score: e = 2^t, contribution
// ep = {e, e*t} accumulated with add.rn.f32x2 into row + col packed sums.
// Warp owns 16 keys (B frags loaded once); col sums live in registers across
// the whole loop; row sums do a u64 quad-shfl per row-group -> smem.
// Identity: <ctx_q,f_q> = 4*ln2 * sw_q/se_q.
// ---------------------------------------------------------------------------
__global__ void __launch_bounds__(TPB) attn_tile_kernel(const float* __restrict__ feats) {
    __shared__ uint32_t sA[128 * 12];       // queries bf16x2, scaled (stride-12: conflict-free)
    __shared__ uint32_t sB[128 * 12];       // keys bf16x2, unscaled
    __shared__ u64 rowpart[8][128];         // per-warp packed row partials

    // decode linear block id -> triangle tile (i, j), i <= j
    int i = 0, rem = blockIdx.x;
    while (rem >= NT - i) { rem -= NT - i; i++; }
    const int j = i + rem;
    const bool diag = (i == j);

    const int tid  = threadIdx.x;
    const int warp = tid >> 5;
    const int lane = tid & 31;
    const int g    = lane >> 2;             // 0..7
    const int tig  = lane & 3;              // 0..3

    // ---- stage both tiles, converting f32 -> bf16 on the fly ----
    {
        const float sc = 0.25f * 1.4426950408889634f;
        const float4* fa = reinterpret_cast<const float4*>(feats) + i * 128 * 4;
        const float4* fb = reinterpret_cast<const float4*>(feats) + j * 128 * 4;
        #pragma unroll
        for (int t = tid; t < 512; t += TPB) {
            int row = t >> 2, f = t & 3;
            float4 va = fa[t];
            float4 vb = fb[t];
            uint2 ua = make_uint2(bf2_u32(__floats2bfloat162_rn(va.x * sc, va.y * sc)),
                                  bf2_u32(__floats2bfloat162_rn(va.z * sc, va.w * sc)));
            uint2 ub = make_uint2(bf2_u32(__floats2bfloat162_rn(vb.x, vb.y)),
                                  bf2_u32(__floats2bfloat162_rn(vb.z, vb.w)));
            *reinterpret_cast<uint2*>(&sA[row * 12 + 2 * f]) = ua;
            *reinterpret_cast<uint2*>(&sB[row * 12 + 2 * f]) = ub;
        }
    }
    __syncthreads();

    // ---- B fragments for this warp's 16 keys (loaded once) ----
    const int wkey = warp * 16;
    const uint32_t b00 = sB[(wkey + g) * 12 + tig];
    const uint32_t b01 = sB[(wkey + g) * 12 + tig + 4];
    const uint32_t b10 = sB[(wkey + 8 + g) * 12 + tig];
    const uint32_t b11 = sB[(wkey + 8 + g) * 12 + tig + 4];

    // packed col accumulators {se, sw}: keys wkey + {2tig, 2tig+1, 8+2tig, 9+2tig}
    u64 c0 = pack2(0.f, 0.f), c1 = c0, c2 = c0, c3 = c0;

    #pragma unroll
    for (int rg = 0; rg < 8; rg++) {
        const int r0 = rg * 16;
        uint32_t a0 = sA[(r0 + g) * 12 + tig];
        uint32_t a1 = sA[(r0 + 8 + g) * 12 + tig];
        uint32_t a2 = sA[(r0 + g) * 12 + tig + 4];
        uint32_t a3 = sA[(r0 + 8 + g) * 12 + tig + 4];

        u64 row0, row1;   // packed row partials for rows r0+g, r0+8+g
        {   // MMA 1: keys wkey + 2tig, wkey + 2tig + 1
            float d0, d1, d2, d3;
            asm volatile(
                "mma.sync.aligned.m16n8k16.row.col.f32.bf16.bf16.f32 "
                "{%0,%1,%2,%3}, {%4,%5,%6,%7}, {%8,%9}, {%10,%11,%12,%13};"
                : "=f"(d0), "=f"(d1), "=f"(d2), "=f"(d3)
                : "r"(a0), "r"(a1), "r"(a2), "r"(a3), "r"(b00), "r"(b01),
                  "f"(0.0f), "f"(0.0f), "f"(0.0f), "f"(0.0f));
            float e0 = ex2_approx(d0), e1 = ex2_approx(d1);
            float e2 = ex2_approx(d2), e3 = ex2_approx(d3);
            u64 ep0 = pack2(e0, e0 * d0);
            u64 ep1 = pack2(e1, e1 * d1);
            u64 ep2 = pack2(e2, e2 * d2);
            u64 ep3 = pack2(e3, e3 * d3);
            row0 = add2(ep0, ep1);          // row r0+g
            row1 = add2(ep2, ep3);          // row r0+8+g
            c0 = add2(c0, add2(ep0, ep2));  // key wkey+2tig
            c1 = add2(c1, add2(ep1, ep3));  // key wkey+2tig+1
        }
        {   // MMA 2: keys wkey + 8 + 2tig, wkey + 9 + 2tig
            float d0, d1, d2, d3;
            asm volatile(
                "mma.sync.aligned.m16n8k16.row.col.f32.bf16.bf16.f32 "
                "{%0,%1,%2,%3}, {%4,%5,%6,%7}, {%8,%9}, {%10,%11,%12,%13};"
                : "=f"(d0), "=f"(d1), "=f"(d2), "=f"(d3)
                : "r"(a0), "r"(a1), "r"(a2), "r"(a3), "r"(b10), "r"(b11),
                  "f"(0.0f), "f"(0.0f), "f"(0.0f), "f"(0.0f));
            float e0 = ex2_approx(d0), e1 = ex2_approx(d1);
            float e2 = ex2_approx(d2), e3 = ex2_approx(d3);
            u64 ep0 = pack2(e0, e0 * d0);
            u64 ep1 = pack2(e1, e1 * d1);
            u64 ep2 = pack2(e2, e2 * d2);
            u64 ep3 = pack2(e3, e3 * d3);
            row0 = add2(row0, add2(ep0, ep1));
            row1 = add2(row1, add2(ep2, ep3));
            c2 = add2(c2, add2(ep0, ep2));  // key wkey+8+2tig
            c3 = add2(c3, add2(ep1, ep3));  // key wkey+9+2tig
        }

        // quad reduce (4 tig lanes) of packed row partials
        row0 = add2(row0, __shfl_xor_sync(0xffffffffu, row0, 1));
        row0 = add2(row0, __shfl_xor_sync(0xffffffffu, row0, 2));
        row1 = add2(row1, __shfl_xor_sync(0xffffffffu, row1, 1));
        row1 = add2(row1, __shfl_xor_sync(0xffffffffu, row1, 2));
        if (tig == 0) {
            rowpart[warp][r0 + g]     = row0;
            rowpart[warp][r0 + 8 + g] = row1;
        }
    }
    __syncthreads();

    // row stats: combine across warps -> slot j, points i*128 + row
    if (tid < 128) {
        u64 acc = rowpart[0][tid];
        #pragma unroll
        for (int w = 1; w < 8; w++) acc = add2(acc, rowpart[w][tid]);
        float se, sw;
        unpack2(acc, se, sw);
        g_part[j][i * 128 + tid] = make_float2(se, sw);
    }

    // col stats: reduce over the 8 g-groups, write slot i, points j*128 + key.
    // Skipped on diagonal tiles (row stats already cover the full tile).
    if (!diag) {
        #pragma unroll
        for (int m = 4; m <= 16; m <<= 1) {
            c0 = add2(c0, __shfl_xor_sync(0xffffffffu, c0, m));
            c1 = add2(c1, __shfl_xor_sync(0xffffffffu, c1, m));
            c2 = add2(c2, __shfl_xor_sync(0xffffffffu, c2, m));
            c3 = add2(c3, __shfl_xor_sync(0xffffffffu, c3, m));
        }
        if (g == 0) {
            const int kb = j * 128 + wkey;
            float se, sw;
            unpack2(c0, se, sw); g_part[i][kb + 2 * tig]     = make_float2(se, sw);
            unpack2(c1, se, sw); g_part[i][kb + 2 * tig + 1] = make_float2(se, sw);
            unpack2(c2, se, sw); g_part[i][kb + 8 + 2 * tig] = make_float2(se, sw);
            unpack2(c3, se, sw); g_part[i][kb + 9 + 2 * tig] = make_float2(se, sw);
        }
    }
}

// ---------------------------------------------------------------------------
// Kernel 2: wide reduction of the 96 partial slots -> per-point w^2.
// 384 blocks x 256 thr; block = 32 points x 8 slot-chunks of 12.
// 12 independent loads per thread (MLP), smem combine across chunks.
// ---------------------------------------------------------------------------
__global__ void __launch_bounds__(256) reduce_kernel() {
    __shared__ float2 red[8][32];
    const int lane  = threadIdx.x & 31;
    const int chunk = threadIdx.x >> 5;
    const int p     = blockIdx.x * 32 + lane;

    float se = 0.f, sw = 0.f;
    #pragma unroll
    for (int s = chunk * 12; s < chunk * 12 + 12; s++) {
        float2 v = g_part[s][p];
        se += v.x; sw += v.y;
    }
    red[chunk][lane] = make_float2(se, sw);
    __syncthreads();

    if (chunk == 0) {
        #pragma unroll
        for (int c = 1; c < 8; c++) {
            float2 v = red[c][lane];
            se += v.x; sw += v.y;
        }
        const float c4ln2 = 4.0f * 0.6931471805599453f;
        float cf = c4ln2 * sw / se;
        float w = 1.0f / (1.0f + __expf(-cf));
        g_w2[p] = w * w;
    }
}

// ---------------------------------------------------------------------------
// Kernel 3: block-local SOP partial M_b = sum_i w_i^2 f_i f_i^T; LAST block
// (atomic counter) reduces partials, L2-normalizes, writes 256-float output.
// (topK=1 -> all points kept; /k cancels in the L2-normalize.)
// ---------------------------------------------------------------------------
__global__ void __launch_bounds__(SOP_BLK) sop_kernel(const float* __restrict__ feats,
                                                      float* __restrict__ out) {
    __shared__ float sf[SOP_BLK][DIM];
    __shared__ float sw2[SOP_BLK];
    __shared__ unsigned int isLast;

    const int tid = threadIdx.x;
    const int b   = blockIdx.x;
    const int p   = b * SOP_BLK + tid;

    sw2[tid] = g_w2[p];

    const float4* fp = reinterpret_cast<const float4*>(feats) + p * 4;
    float4 f0 = fp[0], f1 = fp[1], f2 = fp[2], f3 = fp[3];
    sf[tid][0]  = f0.x; sf[tid][1]  = f0.y; sf[tid][2]  = f0.z; sf[tid][3]  = f0.w;
    sf[tid][4]  = f1.x; sf[tid][5]  = f1.y; sf[tid][6]  = f1.z; sf[tid][7]  = f1.w;
    sf[tid][8]  = f2.x; sf[tid][9]  = f2.y; sf[tid][10] = f2.z; sf[tid][11] = f2.w;
    sf[tid][12] = f3.x; sf[tid][13] = f3.y; sf[tid][14] = f3.z; sf[tid][15] = f3.w;
    __syncthreads();

    const int d = tid >> 4;
    const int e = tid & 15;
    float acc = 0.0f;
    #pragma unroll 8
    for (int i = 0; i < SOP_BLK; i++) {
        acc = fmaf(sw2[i] * sf[i][d], sf[i][e], acc);
    }
    g_Mpart[b][tid] = acc;

    // ---- last-block finalize (deterministic; counter self-resets) ----
    __threadfence();
    if (tid == 0) isLast = (atomicAdd(&g_cnt, 1u) == SOP_BLOCKS - 1) ? 1u : 0u;
    __syncthreads();
    if (isLast) {
        __threadfence();
        float v = 0.0f;
        #pragma unroll 8
        for (int bb = 0; bb < SOP_BLOCKS; bb++) v += g_Mpart[bb][tid];

        __syncthreads();          // sw2 reuse safe
        sw2[tid] = v * v;
        __syncthreads();
        #pragma unroll
        for (int o = 128; o > 0; o >>= 1) {
            if (tid < o) sw2[tid] += sw2[tid + o];
            __syncthreads();
        }
        float inv = 1.0f / sqrtf(sw2[0]);
        out[tid] = v * inv;
        if (tid == 0) g_cnt = 0;
    }
}

// ---------------------------------------------------------------------------
extern "C" void kernel_launch(void* const* d_in, const int* in_sizes, int n_in,
                              void* d_out, int out_size) {
    const float* feats = (const float*)d_in[0];
    float* out = (float*)d_out;

    attn_tile_kernel<<<NPAIRS, TPB>>>(feats);
    reduce_kernel<<<NPTS / 32, 256>>>();
    sop_kernel<<<SOP_BLOCKS, SOP_BLK>>>(feats, out);
}